// round 3
// baseline (speedup 1.0000x reference)
#include <cuda_runtime.h>

#define Bn 4096
#define Tn 128
#define Dn 32
#define Hn 64
#define Gn 192   // 3*H

#define EPW 4            // batch elements per warp
#define NWARP 8
#define TPB (NWARP * 32) // 256 threads
#define EPB (EPW * NWARP) // 32 elements per block

// shared memory layout (floats)
#define OFF_WIH0 0
#define OFF_WHH0 (OFF_WIH0 + Dn * Gn)   // 6144
#define OFF_WIH1 (OFF_WHH0 + Hn * Gn)   // 18432
#define OFF_WHH1 (OFF_WIH1 + Hn * Gn)   // 30720
#define OFF_H1   (OFF_WHH1 + Hn * Gn)   // 43008
#define OFF_H2   (OFF_H1 + EPB * Hn)    // 45056
#define OFF_X    (OFF_H2 + EPB * Hn)    // 47104
#define SMEM_FLOATS (OFF_X + EPB * Dn)  // 48128 floats = 192512 bytes

__device__ __forceinline__ float sigmoid_f(float x) {
    x = fminf(fmaxf(x, -30.0f), 30.0f);
    return __fdividef(1.0f, 1.0f + __expf(-x));
}
__device__ __forceinline__ float tanh_f(float x) {
    x = fminf(fmaxf(x, -15.0f), 15.0f);
    float e = __expf(-2.0f * x);
    return __fdividef(1.0f - e, 1.0f + e);
}

__global__ void __launch_bounds__(TPB, 1)
gru_fused_kernel(const float* __restrict__ x,
                 const float* __restrict__ W_ih0, const float* __restrict__ W_hh0,
                 const float* __restrict__ b_ih0, const float* __restrict__ b_hh0,
                 const float* __restrict__ W_ih1, const float* __restrict__ W_hh1,
                 const float* __restrict__ b_ih1, const float* __restrict__ b_hh1,
                 const float* __restrict__ fc_w, const float* __restrict__ fc_b,
                 float* __restrict__ out)
{
    extern __shared__ float sm[];
    float* s_wih0 = sm + OFF_WIH0;
    float* s_whh0 = sm + OFF_WHH0;
    float* s_wih1 = sm + OFF_WIH1;
    float* s_whh1 = sm + OFF_WHH1;

    const int tid = threadIdx.x;

    // Load weights transposed: s[k*Gn + g] = W[g*K + k]  (lane-consecutive LDS later)
    for (int idx = tid; idx < Gn * Dn; idx += TPB) {
        int g = idx / Dn, k = idx - g * Dn;
        s_wih0[k * Gn + g] = W_ih0[idx];
    }
    for (int idx = tid; idx < Gn * Hn; idx += TPB) {
        int g = idx / Hn, k = idx - g * Hn;
        s_whh0[k * Gn + g] = W_hh0[idx];
        s_wih1[k * Gn + g] = W_ih1[idx];
        s_whh1[k * Gn + g] = W_hh1[idx];
    }
    __syncthreads();

    const int warp = tid >> 5;
    const int lane = tid & 31;
    const int eb = blockIdx.x * EPB + warp * EPW;   // first batch element of this warp

    float* s_h1 = sm + OFF_H1 + warp * EPW * Hn;    // [EPW][Hn], warp-private
    float* s_h2 = sm + OFF_H2 + warp * EPW * Hn;
    float* s_x  = sm + OFF_X  + warp * EPW * Dn;    // [EPW][Dn]

#pragma unroll
    for (int e = 0; e < EPW; ++e) {
        s_h1[e * Hn + lane] = 0.0f; s_h1[e * Hn + lane + 32] = 0.0f;
        s_h2[e * Hn + lane] = 0.0f; s_h2[e * Hn + lane + 32] = 0.0f;
    }
    __syncwarp();

    // Per-lane bias constants (lane owns gate rows {lane, lane+32} of r, z, n)
    const float B0r0  = b_ih0[lane]       + b_hh0[lane];
    const float B0r1  = b_ih0[lane + 32]  + b_hh0[lane + 32];
    const float B0z0  = b_ih0[lane + 64]  + b_hh0[lane + 64];
    const float B0z1  = b_ih0[lane + 96]  + b_hh0[lane + 96];
    const float B0xn0 = b_ih0[lane + 128];
    const float B0xn1 = b_ih0[lane + 160];
    const float B0hn0 = b_hh0[lane + 128];
    const float B0hn1 = b_hh0[lane + 160];

    const float B1r0  = b_ih1[lane]       + b_hh1[lane];
    const float B1r1  = b_ih1[lane + 32]  + b_hh1[lane + 32];
    const float B1z0  = b_ih1[lane + 64]  + b_hh1[lane + 64];
    const float B1z1  = b_ih1[lane + 96]  + b_hh1[lane + 96];
    const float B1xn0 = b_ih1[lane + 128];
    const float B1xn1 = b_ih1[lane + 160];
    const float B1hn0 = b_hh1[lane + 128];
    const float B1hn1 = b_hh1[lane + 160];

    float ar0[EPW], ar1[EPW], az0[EPW], az1[EPW];
    float axn0[EPW], axn1[EPW], ahn0[EPW], ahn1[EPW];

    for (int t = 0; t < Tn; ++t) {
        // ---- stage x[b, t, :] for the warp's 4 elements (coalesced 128B each) ----
#pragma unroll
        for (int e = 0; e < EPW; ++e)
            s_x[e * Dn + lane] = x[((eb + e) * Tn + t) * Dn + lane];
        __syncwarp();

        // ================= layer 0 =================
#pragma unroll
        for (int e = 0; e < EPW; ++e) {
            ar0[e] = B0r0;  ar1[e] = B0r1;
            az0[e] = B0z0;  az1[e] = B0z1;
            axn0[e] = B0xn0; axn1[e] = B0xn1;
            ahn0[e] = B0hn0; ahn1[e] = B0hn1;
        }

        // x-side: W_ih0 @ x
#pragma unroll 4
        for (int k = 0; k < Dn; ++k) {
            const float* w = s_wih0 + k * Gn + lane;
            float wr0 = w[0],   wr1 = w[32];
            float wz0 = w[64],  wz1 = w[96];
            float wn0 = w[128], wn1 = w[160];
#pragma unroll
            for (int e = 0; e < EPW; ++e) {
                float xv = s_x[e * Dn + k];
                ar0[e]  = fmaf(wr0, xv, ar0[e]);  ar1[e]  = fmaf(wr1, xv, ar1[e]);
                az0[e]  = fmaf(wz0, xv, az0[e]);  az1[e]  = fmaf(wz1, xv, az1[e]);
                axn0[e] = fmaf(wn0, xv, axn0[e]); axn1[e] = fmaf(wn1, xv, axn1[e]);
            }
        }

        // h-side: W_hh0 @ h1
#pragma unroll 4
        for (int k = 0; k < Hn; ++k) {
            const float* w = s_whh0 + k * Gn + lane;
            float wr0 = w[0],   wr1 = w[32];
            float wz0 = w[64],  wz1 = w[96];
            float wn0 = w[128], wn1 = w[160];
#pragma unroll
            for (int e = 0; e < EPW; ++e) {
                float hv = s_h1[e * Hn + k];
                ar0[e]  = fmaf(wr0, hv, ar0[e]);  ar1[e]  = fmaf(wr1, hv, ar1[e]);
                az0[e]  = fmaf(wz0, hv, az0[e]);  az1[e]  = fmaf(wz1, hv, az1[e]);
                ahn0[e] = fmaf(wn0, hv, ahn0[e]); ahn1[e] = fmaf(wn1, hv, ahn1[e]);
            }
        }

        // gates -> h1_new
        float hA[EPW], hB[EPW];
#pragma unroll
        for (int e = 0; e < EPW; ++e) {
            float r0 = sigmoid_f(ar0[e]), r1 = sigmoid_f(ar1[e]);
            float z0 = sigmoid_f(az0[e]), z1 = sigmoid_f(az1[e]);
            float n0 = tanh_f(fmaf(r0, ahn0[e], axn0[e]));
            float n1 = tanh_f(fmaf(r1, ahn1[e], axn1[e]));
            float h0 = s_h1[e * Hn + lane];
            float h1 = s_h1[e * Hn + lane + 32];
            hA[e] = fmaf(z0, h0 - n0, n0);   // (1-z)n + z h
            hB[e] = fmaf(z1, h1 - n1, n1);
        }
        __syncwarp();
#pragma unroll
        for (int e = 0; e < EPW; ++e) {
            s_h1[e * Hn + lane]      = hA[e];
            s_h1[e * Hn + lane + 32] = hB[e];
        }
        __syncwarp();

        // ================= layer 1 =================
#pragma unroll
        for (int e = 0; e < EPW; ++e) {
            ar0[e] = B1r0;  ar1[e] = B1r1;
            az0[e] = B1z0;  az1[e] = B1z1;
            axn0[e] = B1xn0; axn1[e] = B1xn1;
            ahn0[e] = B1hn0; ahn1[e] = B1hn1;
        }

        // fused x-side (input = h1_new) and h-side (h2) over shared k
#pragma unroll 2
        for (int k = 0; k < Hn; ++k) {
            const float* wi = s_wih1 + k * Gn + lane;
            const float* wh = s_whh1 + k * Gn + lane;
            float ir0 = wi[0],   ir1 = wi[32];
            float iz0 = wi[64],  iz1 = wi[96];
            float in0 = wi[128], in1 = wi[160];
            float hr0 = wh[0],   hr1 = wh[32];
            float hz0 = wh[64],  hz1 = wh[96];
            float hn0w = wh[128], hn1w = wh[160];
#pragma unroll
            for (int e = 0; e < EPW; ++e) {
                float a = s_h1[e * Hn + k];   // layer-1 input
                float b = s_h2[e * Hn + k];   // layer-1 hidden (prev t)
                ar0[e]  = fmaf(ir0, a, ar0[e]);  ar0[e]  = fmaf(hr0, b, ar0[e]);
                ar1[e]  = fmaf(ir1, a, ar1[e]);  ar1[e]  = fmaf(hr1, b, ar1[e]);
                az0[e]  = fmaf(iz0, a, az0[e]);  az0[e]  = fmaf(hz0, b, az0[e]);
                az1[e]  = fmaf(iz1, a, az1[e]);  az1[e]  = fmaf(hz1, b, az1[e]);
                axn0[e] = fmaf(in0, a, axn0[e]); axn1[e] = fmaf(in1, a, axn1[e]);
                ahn0[e] = fmaf(hn0w, b, ahn0[e]); ahn1[e] = fmaf(hn1w, b, ahn1[e]);
            }
        }

        // gates -> h2_new
#pragma unroll
        for (int e = 0; e < EPW; ++e) {
            float r0 = sigmoid_f(ar0[e]), r1 = sigmoid_f(ar1[e]);
            float z0 = sigmoid_f(az0[e]), z1 = sigmoid_f(az1[e]);
            float n0 = tanh_f(fmaf(r0, ahn0[e], axn0[e]));
            float n1 = tanh_f(fmaf(r1, ahn1[e], axn1[e]));
            float h0 = s_h2[e * Hn + lane];
            float h1 = s_h2[e * Hn + lane + 32];
            hA[e] = fmaf(z0, h0 - n0, n0);
            hB[e] = fmaf(z1, h1 - n1, n1);
        }
        __syncwarp();
#pragma unroll
        for (int e = 0; e < EPW; ++e) {
            s_h2[e * Hn + lane]      = hA[e];
            s_h2[e * Hn + lane + 32] = hB[e];
        }
        __syncwarp();
    }

    // ---- FC head: out[b] = fc_w . h2_final + fc_b ----
    const float fw0 = fc_w[lane];
    const float fw1 = fc_w[lane + 32];
    const float fb  = fc_b[0];
#pragma unroll
    for (int e = 0; e < EPW; ++e) {
        float v = fw0 * s_h2[e * Hn + lane] + fw1 * s_h2[e * Hn + lane + 32];
#pragma unroll
        for (int off = 16; off > 0; off >>= 1)
            v += __shfl_xor_sync(0xffffffffu, v, off);
        if (lane == 0) out[eb + e] = v + fb;
    }
}

extern "C" void kernel_launch(void* const* d_in, const int* in_sizes, int n_in,
                              void* d_out, int out_size)
{
    const float* x     = (const float*)d_in[0];
    const float* W_ih0 = (const float*)d_in[1];
    const float* W_hh0 = (const float*)d_in[2];
    const float* b_ih0 = (const float*)d_in[3];
    const float* b_hh0 = (const float*)d_in[4];
    const float* W_ih1 = (const float*)d_in[5];
    const float* W_hh1 = (const float*)d_in[6];
    const float* b_ih1 = (const float*)d_in[7];
    const float* b_hh1 = (const float*)d_in[8];
    const float* fc_w  = (const float*)d_in[9];
    const float* fc_b  = (const float*)d_in[10];
    float* out = (float*)d_out;

    int batch = in_sizes[0] / (Tn * Dn);   // 4096
    int grid = batch / EPB;                // 128 blocks

    size_t smem = (size_t)SMEM_FLOATS * sizeof(float);  // 192512 B
    cudaFuncSetAttribute(gru_fused_kernel,
                         cudaFuncAttributeMaxDynamicSharedMemorySize, (int)smem);

    gru_fused_kernel<<<grid, TPB, smem>>>(x, W_ih0, W_hh0, b_ih0, b_hh0,
                                          W_ih1, W_hh1, b_ih1, b_hh1,
                                          fc_w, fc_b, out);
}

// round 4
// speedup vs baseline: 1.6744x; 1.6744x over previous
#include <cuda_runtime.h>

typedef unsigned long long u64;

#define Bn 4096
#define Tn 128
#define Dn 32
#define Hn 64
#define Gn 192   // 3*H

#define EPW 4            // batch elements per warp
#define NWARP 8
#define TPB (NWARP * 32) // 256 threads
#define EPB (EPW * NWARP) // 32 elements per block

// shared memory layout (float units). Weight matrices stored transposed with the
// (lane, lane+32) gate-row pair adjacent:  addr = k*192 + gate*64 + (r&31)*2 + (r>>5)
#define OFF_W0X 0
#define OFF_W0H (OFF_W0X + Dn * Gn)     // 6144
#define OFF_W1I (OFF_W0H + Hn * Gn)     // 18432
#define OFF_W1H (OFF_W1I + Hn * Gn)     // 30720
#define OFF_H1  (OFF_W1H + Hn * Gn)     // 43008  (duplicated pairs: 2 floats per h value)
#define OFF_H2  (OFF_H1 + EPB * Hn * 2) // 51200
#define OFF_X   (OFF_H2 + EPB * Hn * 2) // 59392
#define SMEM_FLOATS (OFF_X + EPB * Dn * 2) // 61440 floats... wait
// 43008 + 4096 = 47104 ; +4096 = 51200 ; +2048 = 53248 floats = 212992 bytes
#undef OFF_H2
#undef OFF_X
#undef SMEM_FLOATS
#define OFF_H2  (OFF_H1 + EPB * Hn * 2)      // 47104
#define OFF_X   (OFF_H2 + EPB * Hn * 2)      // 51200
#define SMEM_FLOATS (OFF_X + EPB * Dn * 2)   // 53248 floats = 212992 B

__device__ __forceinline__ void ffma2(u64& d, u64 a, u64 b) {
    asm("fma.rn.f32x2 %0, %1, %2, %0;" : "+l"(d) : "l"(a), "l"(b));
}
__device__ __forceinline__ u64 pack2(float lo, float hi) {
    u64 r; asm("mov.b64 %0, {%1, %2};" : "=l"(r) : "f"(lo), "f"(hi)); return r;
}
__device__ __forceinline__ void unpack2(u64 v, float& lo, float& hi) {
    asm("mov.b64 {%0, %1}, %2;" : "=f"(lo), "=f"(hi) : "l"(v));
}

__device__ __forceinline__ float sigmoid_f(float x) {
    return __fdividef(1.0f, 1.0f + __expf(-x));
}
__device__ __forceinline__ float tanh_f(float x) {
    float e = __expf(-2.0f * x);
    return __fdividef(1.0f - e, 1.0f + e);
}

__global__ void __launch_bounds__(TPB, 1)
gru_fused_kernel(const float* __restrict__ x,
                 const float* __restrict__ W_ih0, const float* __restrict__ W_hh0,
                 const float* __restrict__ b_ih0, const float* __restrict__ b_hh0,
                 const float* __restrict__ W_ih1, const float* __restrict__ W_hh1,
                 const float* __restrict__ b_ih1, const float* __restrict__ b_hh1,
                 const float* __restrict__ fc_w, const float* __restrict__ fc_b,
                 float* __restrict__ out)
{
    extern __shared__ float sm[];
    const int tid = threadIdx.x;

    // ---- stage weights transposed + gate-row-pair interleaved ----
    for (int idx = tid; idx < Gn * Dn; idx += TPB) {
        int g = idx / Dn, k = idx - g * Dn;
        int gate = g >> 6, r = g & 63;
        sm[OFF_W0X + k * Gn + gate * 64 + (r & 31) * 2 + (r >> 5)] = W_ih0[idx];
    }
    for (int idx = tid; idx < Gn * Hn; idx += TPB) {
        int g = idx / Hn, k = idx - g * Hn;
        int gate = g >> 6, r = g & 63;
        int d = k * Gn + gate * 64 + (r & 31) * 2 + (r >> 5);
        sm[OFF_W0H + d] = W_hh0[idx];
        sm[OFF_W1I + d] = W_ih1[idx];
        sm[OFF_W1H + d] = W_hh1[idx];
    }
    __syncthreads();

    const int warp = tid >> 5;
    const int lane = tid & 31;
    const int eb = blockIdx.x * EPB + warp * EPW;

    const u64* w0x = (const u64*)(sm + OFF_W0X);   // [k][96] u64 pairs
    const u64* w0h = (const u64*)(sm + OFF_W0H);
    const u64* w1i = (const u64*)(sm + OFF_W1I);
    const u64* w1h = (const u64*)(sm + OFF_W1H);
    u64* s_h1 = (u64*)(sm + OFF_H1) + warp * EPW * Hn;  // duplicated (v,v) pairs
    u64* s_h2 = (u64*)(sm + OFF_H2) + warp * EPW * Hn;
    u64* s_x  = (u64*)(sm + OFF_X)  + warp * EPW * Dn;

#pragma unroll
    for (int e = 0; e < EPW; ++e) {
        s_h1[e * Hn + lane] = 0ull; s_h1[e * Hn + lane + 32] = 0ull;
        s_h2[e * Hn + lane] = 0ull; s_h2[e * Hn + lane + 32] = 0ull;
    }
    __syncwarp();

    // packed bias pairs (rows lane, lane+32)
    const u64 B0r  = pack2(b_ih0[lane]      + b_hh0[lane],
                           b_ih0[lane + 32] + b_hh0[lane + 32]);
    const u64 B0z  = pack2(b_ih0[lane + 64] + b_hh0[lane + 64],
                           b_ih0[lane + 96] + b_hh0[lane + 96]);
    const u64 B0xn = pack2(b_ih0[lane + 128], b_ih0[lane + 160]);
    const u64 B0hn = pack2(b_hh0[lane + 128], b_hh0[lane + 160]);
    const u64 B1r  = pack2(b_ih1[lane]      + b_hh1[lane],
                           b_ih1[lane + 32] + b_hh1[lane + 32]);
    const u64 B1z  = pack2(b_ih1[lane + 64] + b_hh1[lane + 64],
                           b_ih1[lane + 96] + b_hh1[lane + 96]);
    const u64 B1xn = pack2(b_ih1[lane + 128], b_ih1[lane + 160]);
    const u64 B1hn = pack2(b_hh1[lane + 128], b_hh1[lane + 160]);

    u64 ar[EPW], az[EPW], axn[EPW], ahn[EPW];
    u64 hA[EPW], hB[EPW];

    // prefetch t=0 x
    float xr[EPW];
#pragma unroll
    for (int e = 0; e < EPW; ++e)
        xr[e] = x[(eb + e) * (Tn * Dn) + lane];

    for (int t = 0; t < Tn; ++t) {
        // stage x duplicated; prefetch next t
#pragma unroll
        for (int e = 0; e < EPW; ++e)
            s_x[e * Dn + lane] = pack2(xr[e], xr[e]);
        __syncwarp();
        if (t + 1 < Tn) {
#pragma unroll
            for (int e = 0; e < EPW; ++e)
                xr[e] = x[((eb + e) * Tn + t + 1) * Dn + lane];
        }

        // ================= layer 0 =================
#pragma unroll
        for (int e = 0; e < EPW; ++e) {
            ar[e] = B0r; az[e] = B0z; axn[e] = B0xn; ahn[e] = B0hn;
        }

#pragma unroll 4
        for (int k = 0; k < Dn; ++k) {
            const u64* w = w0x + k * 96 + lane;
            u64 wr = w[0], wz = w[32], wn = w[64];
#pragma unroll
            for (int e = 0; e < EPW; ++e) {
                u64 xv = s_x[e * Dn + k];
                ffma2(ar[e], wr, xv);
                ffma2(az[e], wz, xv);
                ffma2(axn[e], wn, xv);
            }
        }
#pragma unroll 4
        for (int k = 0; k < Hn; ++k) {
            const u64* w = w0h + k * 96 + lane;
            u64 wr = w[0], wz = w[32], wn = w[64];
#pragma unroll
            for (int e = 0; e < EPW; ++e) {
                u64 hv = s_h1[e * Hn + k];
                ffma2(ar[e], wr, hv);
                ffma2(az[e], wz, hv);
                ffma2(ahn[e], wn, hv);
            }
        }

#pragma unroll
        for (int e = 0; e < EPW; ++e) {
            float vr0, vr1, vz0, vz1, xn0, xn1, hn0, hn1;
            unpack2(ar[e], vr0, vr1);  unpack2(az[e], vz0, vz1);
            unpack2(axn[e], xn0, xn1); unpack2(ahn[e], hn0, hn1);
            float r0 = sigmoid_f(vr0), r1 = sigmoid_f(vr1);
            float z0 = sigmoid_f(vz0), z1 = sigmoid_f(vz1);
            float n0 = tanh_f(fmaf(r0, hn0, xn0));
            float n1 = tanh_f(fmaf(r1, hn1, xn1));
            float hp0, hp1, du;
            unpack2(s_h1[e * Hn + lane],      hp0, du);
            unpack2(s_h1[e * Hn + lane + 32], hp1, du);
            float hv0 = fmaf(z0, hp0 - n0, n0);
            float hv1 = fmaf(z1, hp1 - n1, n1);
            hA[e] = pack2(hv0, hv0);
            hB[e] = pack2(hv1, hv1);
        }
        __syncwarp();
#pragma unroll
        for (int e = 0; e < EPW; ++e) {
            s_h1[e * Hn + lane]      = hA[e];
            s_h1[e * Hn + lane + 32] = hB[e];
        }
        __syncwarp();

        // ================= layer 1 =================
#pragma unroll
        for (int e = 0; e < EPW; ++e) {
            ar[e] = B1r; az[e] = B1z; axn[e] = B1xn; ahn[e] = B1hn;
        }

#pragma unroll 2
        for (int k = 0; k < Hn; ++k) {
            const u64* wi = w1i + k * 96 + lane;
            const u64* wh = w1h + k * 96 + lane;
            u64 ir = wi[0], iz = wi[32], in = wi[64];
            u64 hr = wh[0], hz = wh[32], hn = wh[64];
#pragma unroll
            for (int e = 0; e < EPW; ++e) {
                u64 a = s_h1[e * Hn + k];
                u64 b = s_h2[e * Hn + k];
                ffma2(ar[e], ir, a);  ffma2(ar[e], hr, b);
                ffma2(az[e], iz, a);  ffma2(az[e], hz, b);
                ffma2(axn[e], in, a); ffma2(ahn[e], hn, b);
            }
        }

#pragma unroll
        for (int e = 0; e < EPW; ++e) {
            float vr0, vr1, vz0, vz1, xn0, xn1, hn0, hn1;
            unpack2(ar[e], vr0, vr1);  unpack2(az[e], vz0, vz1);
            unpack2(axn[e], xn0, xn1); unpack2(ahn[e], hn0, hn1);
            float r0 = sigmoid_f(vr0), r1 = sigmoid_f(vr1);
            float z0 = sigmoid_f(vz0), z1 = sigmoid_f(vz1);
            float n0 = tanh_f(fmaf(r0, hn0, xn0));
            float n1 = tanh_f(fmaf(r1, hn1, xn1));
            float hp0, hp1, du;
            unpack2(s_h2[e * Hn + lane],      hp0, du);
            unpack2(s_h2[e * Hn + lane + 32], hp1, du);
            float hv0 = fmaf(z0, hp0 - n0, n0);
            float hv1 = fmaf(z1, hp1 - n1, n1);
            hA[e] = pack2(hv0, hv0);
            hB[e] = pack2(hv1, hv1);
        }
        __syncwarp();
#pragma unroll
        for (int e = 0; e < EPW; ++e) {
            s_h2[e * Hn + lane]      = hA[e];
            s_h2[e * Hn + lane + 32] = hB[e];
        }
        __syncwarp();
    }

    // ---- FC head ----
    const float fw0 = fc_w[lane];
    const float fw1 = fc_w[lane + 32];
    const float fb  = fc_b[0];
#pragma unroll
    for (int e = 0; e < EPW; ++e) {
        float h0, h1, du;
        unpack2(s_h2[e * Hn + lane],      h0, du);
        unpack2(s_h2[e * Hn + lane + 32], h1, du);
        float v = fw0 * h0 + fw1 * h1;
#pragma unroll
        for (int off = 16; off > 0; off >>= 1)
            v += __shfl_xor_sync(0xffffffffu, v, off);
        if (lane == 0) out[eb + e] = v + fb;
    }
}

extern "C" void kernel_launch(void* const* d_in, const int* in_sizes, int n_in,
                              void* d_out, int out_size)
{
    const float* x     = (const float*)d_in[0];
    const float* W_ih0 = (const float*)d_in[1];
    const float* W_hh0 = (const float*)d_in[2];
    const float* b_ih0 = (const float*)d_in[3];
    const float* b_hh0 = (const float*)d_in[4];
    const float* W_ih1 = (const float*)d_in[5];
    const float* W_hh1 = (const float*)d_in[6];
    const float* b_ih1 = (const float*)d_in[7];
    const float* b_hh1 = (const float*)d_in[8];
    const float* fc_w  = (const float*)d_in[9];
    const float* fc_b  = (const float*)d_in[10];
    float* out = (float*)d_out;

    int batch = in_sizes[0] / (Tn * Dn);   // 4096
    int grid = batch / EPB;                // 128 blocks

    size_t smem = (size_t)SMEM_FLOATS * sizeof(float);  // 212992 B
    cudaFuncSetAttribute(gru_fused_kernel,
                         cudaFuncAttributeMaxDynamicSharedMemorySize, (int)smem);

    gru_fused_kernel<<<grid, TPB, smem>>>(x, W_ih0, W_hh0, b_ih0, b_hh0,
                                          W_ih1, W_hh1, b_ih1, b_hh1,
                                          fc_w, fc_b, out);
}

// round 5
// speedup vs baseline: 1.8014x; 1.0758x over previous
#include <cuda_runtime.h>

typedef unsigned long long u64;

#define Bn 4096
#define Tn 128
#define Dn 32
#define Hn 64
#define Gn 192   // 3*H

#define EPW 8            // batch elements per warp
#define NWARP 4
#define TPB (NWARP * 32) // 128 threads
#define EPB (EPW * NWARP) // 32 elements per block

// Shared layout (float units). Weights stored as [k_quad][192 rows][4 k's]:
//   s[(k>>2)*768 + g*4 + (k&3)] = W[g][k]
#define OFF_W0X 0                        // [8][192][4]  = 6144
#define OFF_W0H (OFF_W0X + 8  * 768)    // 6144, [16][192][4] = 12288
#define OFF_W1I (OFF_W0H + 16 * 768)    // 18432
#define OFF_W1H (OFF_W1I + 16 * 768)    // 30720
#define OFF_H1  (OFF_W1H + 16 * 768)    // 43008, [32 elems][64]
#define OFF_H2  (OFF_H1 + EPB * Hn)     // 45056
#define OFF_X   (OFF_H2 + EPB * Hn)     // 47104, [32 elems][32]
#define SMEM_FLOATS (OFF_X + EPB * Dn)  // 48128 floats = 192512 B

__device__ __forceinline__ void ffma2(u64& d, u64 a, u64 b) {
    asm("fma.rn.f32x2 %0, %1, %2, %0;" : "+l"(d) : "l"(a), "l"(b));
}
__device__ __forceinline__ float hsum2(u64 v) {
    float lo, hi;
    asm("mov.b64 {%0, %1}, %2;" : "=f"(lo), "=f"(hi) : "l"(v));
    return lo + hi;
}
__device__ __forceinline__ float sigmoid_f(float x) {
    return __fdividef(1.0f, 1.0f + __expf(-x));
}
__device__ __forceinline__ float tanh_f(float x) {
    float e = __expf(-2.0f * x);
    return __fdividef(1.0f - e, 1.0f + e);
}

struct u64x2 { u64 a, b; };
__device__ __forceinline__ u64x2 lds128(const float* p) {
    u64x2 r;
    const ulonglong2* q = (const ulonglong2*)p;
    ulonglong2 v = *q;
    r.a = v.x; r.b = v.y;
    return r;
}

__global__ void __launch_bounds__(TPB, 1)
gru_fused_kernel(const float* __restrict__ x,
                 const float* __restrict__ W_ih0, const float* __restrict__ W_hh0,
                 const float* __restrict__ b_ih0, const float* __restrict__ b_hh0,
                 const float* __restrict__ W_ih1, const float* __restrict__ W_hh1,
                 const float* __restrict__ b_ih1, const float* __restrict__ b_hh1,
                 const float* __restrict__ fc_w, const float* __restrict__ fc_b,
                 float* __restrict__ out)
{
    extern __shared__ float sm[];
    const int tid = threadIdx.x;

    // ---- stage weights: s[(k>>2)*768 + g*4 + (k&3)] = W[g*K + k] ----
    for (int idx = tid; idx < Gn * Dn; idx += TPB) {
        int g = idx / Dn, k = idx - g * Dn;
        sm[OFF_W0X + (k >> 2) * 768 + g * 4 + (k & 3)] = W_ih0[idx];
    }
    for (int idx = tid; idx < Gn * Hn; idx += TPB) {
        int g = idx / Hn, k = idx - g * Hn;
        int d = (k >> 2) * 768 + g * 4 + (k & 3);
        sm[OFF_W0H + d] = W_hh0[idx];
        sm[OFF_W1I + d] = W_ih1[idx];
        sm[OFF_W1H + d] = W_hh1[idx];
    }
    __syncthreads();

    const int warp = tid >> 5;
    const int lane = tid & 31;
    const int eb = blockIdx.x * EPB + warp * EPW;

    float* s_h1 = sm + OFF_H1 + warp * EPW * Hn;   // warp-private [EPW][64]
    float* s_h2 = sm + OFF_H2 + warp * EPW * Hn;
    float* s_x  = sm + OFF_X  + warp * EPW * Dn;   // [EPW][32]

#pragma unroll
    for (int e = 0; e < EPW; ++e) {
        s_h1[e * Hn + lane] = 0.0f; s_h1[e * Hn + lane + 32] = 0.0f;
        s_h2[e * Hn + lane] = 0.0f; s_h2[e * Hn + lane + 32] = 0.0f;
    }
    __syncwarp();

    // per-lane scalar biases (lane owns gate rows lane, lane+32)
    const float B0r0  = b_ih0[lane]       + b_hh0[lane];
    const float B0r1  = b_ih0[lane + 32]  + b_hh0[lane + 32];
    const float B0z0  = b_ih0[lane + 64]  + b_hh0[lane + 64];
    const float B0z1  = b_ih0[lane + 96]  + b_hh0[lane + 96];
    const float B0xn0 = b_ih0[lane + 128];
    const float B0xn1 = b_ih0[lane + 160];
    const float B0hn0 = b_hh0[lane + 128];
    const float B0hn1 = b_hh0[lane + 160];
    const float B1r0  = b_ih1[lane]       + b_hh1[lane];
    const float B1r1  = b_ih1[lane + 32]  + b_hh1[lane + 32];
    const float B1z0  = b_ih1[lane + 64]  + b_hh1[lane + 64];
    const float B1z1  = b_ih1[lane + 96]  + b_hh1[lane + 96];
    const float B1xn0 = b_ih1[lane + 128];
    const float B1xn1 = b_ih1[lane + 160];
    const float B1hn0 = b_hh1[lane + 128];
    const float B1hn1 = b_hh1[lane + 160];

    // weight smem bases for this lane's 6 output rows (float4 index = row*4)
    const int oR0 = lane * 4,           oR1 = (lane + 32) * 4;
    const int oZ0 = (lane + 64) * 4,    oZ1 = (lane + 96) * 4;
    const int oN0 = (lane + 128) * 4,   oN1 = (lane + 160) * 4;

    u64 ar0[EPW], ar1[EPW], az0[EPW], az1[EPW];
    u64 axn0[EPW], axn1[EPW], ahn0[EPW], ahn1[EPW];

    // prefetch t=0 x
    float xr[EPW];
#pragma unroll
    for (int e = 0; e < EPW; ++e)
        xr[e] = x[(eb + e) * (Tn * Dn) + lane];

    for (int t = 0; t < Tn; ++t) {
        // stage x (natural layout), prefetch next t
#pragma unroll
        for (int e = 0; e < EPW; ++e)
            s_x[e * Dn + lane] = xr[e];
        __syncwarp();
        if (t + 1 < Tn) {
#pragma unroll
            for (int e = 0; e < EPW; ++e)
                xr[e] = x[((eb + e) * Tn + t + 1) * Dn + lane];
        }

        // ================= layer 0 =================
#pragma unroll
        for (int e = 0; e < EPW; ++e) {
            ar0[e] = 0; ar1[e] = 0; az0[e] = 0; az1[e] = 0;
            axn0[e] = 0; axn1[e] = 0; ahn0[e] = 0; ahn1[e] = 0;
        }

        // x-side: 8 quads of k over Dn=32
#pragma unroll 2
        for (int q = 0; q < Dn / 4; ++q) {
            const float* wq = sm + OFF_W0X + q * 768;
            u64x2 wr0 = lds128(wq + oR0), wr1 = lds128(wq + oR1);
            u64x2 wz0 = lds128(wq + oZ0), wz1 = lds128(wq + oZ1);
            u64x2 wn0 = lds128(wq + oN0), wn1 = lds128(wq + oN1);
#pragma unroll
            for (int e = 0; e < EPW; ++e) {
                u64x2 xv = lds128(s_x + e * Dn + q * 4);   // broadcast
                ffma2(ar0[e], wr0.a, xv.a);  ffma2(ar0[e], wr0.b, xv.b);
                ffma2(ar1[e], wr1.a, xv.a);  ffma2(ar1[e], wr1.b, xv.b);
                ffma2(az0[e], wz0.a, xv.a);  ffma2(az0[e], wz0.b, xv.b);
                ffma2(az1[e], wz1.a, xv.a);  ffma2(az1[e], wz1.b, xv.b);
                ffma2(axn0[e], wn0.a, xv.a); ffma2(axn0[e], wn0.b, xv.b);
                ffma2(axn1[e], wn1.a, xv.a); ffma2(axn1[e], wn1.b, xv.b);
            }
        }
        // h-side: 16 quads over Hn=64
#pragma unroll 2
        for (int q = 0; q < Hn / 4; ++q) {
            const float* wq = sm + OFF_W0H + q * 768;
            u64x2 wr0 = lds128(wq + oR0), wr1 = lds128(wq + oR1);
            u64x2 wz0 = lds128(wq + oZ0), wz1 = lds128(wq + oZ1);
            u64x2 wn0 = lds128(wq + oN0), wn1 = lds128(wq + oN1);
#pragma unroll
            for (int e = 0; e < EPW; ++e) {
                u64x2 hv = lds128(s_h1 + e * Hn + q * 4);
                ffma2(ar0[e], wr0.a, hv.a);  ffma2(ar0[e], wr0.b, hv.b);
                ffma2(ar1[e], wr1.a, hv.a);  ffma2(ar1[e], wr1.b, hv.b);
                ffma2(az0[e], wz0.a, hv.a);  ffma2(az0[e], wz0.b, hv.b);
                ffma2(az1[e], wz1.a, hv.a);  ffma2(az1[e], wz1.b, hv.b);
                ffma2(ahn0[e], wn0.a, hv.a); ffma2(ahn0[e], wn0.b, hv.b);
                ffma2(ahn1[e], wn1.a, hv.a); ffma2(ahn1[e], wn1.b, hv.b);
            }
        }

        // gates -> h1_new
        float hA[EPW], hB[EPW];
#pragma unroll
        for (int e = 0; e < EPW; ++e) {
            float r0 = sigmoid_f(hsum2(ar0[e]) + B0r0);
            float r1 = sigmoid_f(hsum2(ar1[e]) + B0r1);
            float z0 = sigmoid_f(hsum2(az0[e]) + B0z0);
            float z1 = sigmoid_f(hsum2(az1[e]) + B0z1);
            float n0 = tanh_f(fmaf(r0, hsum2(ahn0[e]) + B0hn0, hsum2(axn0[e]) + B0xn0));
            float n1 = tanh_f(fmaf(r1, hsum2(ahn1[e]) + B0hn1, hsum2(axn1[e]) + B0xn1));
            float hp0 = s_h1[e * Hn + lane];
            float hp1 = s_h1[e * Hn + lane + 32];
            hA[e] = fmaf(z0, hp0 - n0, n0);
            hB[e] = fmaf(z1, hp1 - n1, n1);
        }
        __syncwarp();
#pragma unroll
        for (int e = 0; e < EPW; ++e) {
            s_h1[e * Hn + lane]      = hA[e];
            s_h1[e * Hn + lane + 32] = hB[e];
        }
        __syncwarp();

        // ================= layer 1 =================
#pragma unroll
        for (int e = 0; e < EPW; ++e) {
            ar0[e] = 0; ar1[e] = 0; az0[e] = 0; az1[e] = 0;
            axn0[e] = 0; axn1[e] = 0; ahn0[e] = 0; ahn1[e] = 0;
        }

#pragma unroll 1
        for (int q = 0; q < Hn / 4; ++q) {
            const float* wqi = sm + OFF_W1I + q * 768;
            const float* wqh = sm + OFF_W1H + q * 768;
            u64x2 ir0 = lds128(wqi + oR0), ir1 = lds128(wqi + oR1);
            u64x2 iz0 = lds128(wqi + oZ0), iz1 = lds128(wqi + oZ1);
            u64x2 in0 = lds128(wqi + oN0), in1 = lds128(wqi + oN1);
            u64x2 hr0 = lds128(wqh + oR0), hr1 = lds128(wqh + oR1);
            u64x2 hz0 = lds128(wqh + oZ0), hz1 = lds128(wqh + oZ1);
            u64x2 hn0 = lds128(wqh + oN0), hn1 = lds128(wqh + oN1);
#pragma unroll
            for (int e = 0; e < EPW; ++e) {
                u64x2 av = lds128(s_h1 + e * Hn + q * 4);  // layer-1 input
                u64x2 bv = lds128(s_h2 + e * Hn + q * 4);  // hidden (prev t)
                ffma2(ar0[e], ir0.a, av.a);  ffma2(ar0[e], ir0.b, av.b);
                ffma2(ar0[e], hr0.a, bv.a);  ffma2(ar0[e], hr0.b, bv.b);
                ffma2(ar1[e], ir1.a, av.a);  ffma2(ar1[e], ir1.b, av.b);
                ffma2(ar1[e], hr1.a, bv.a);  ffma2(ar1[e], hr1.b, bv.b);
                ffma2(az0[e], iz0.a, av.a);  ffma2(az0[e], iz0.b, av.b);
                ffma2(az0[e], hz0.a, bv.a);  ffma2(az0[e], hz0.b, bv.b);
                ffma2(az1[e], iz1.a, av.a);  ffma2(az1[e], iz1.b, av.b);
                ffma2(az1[e], hz1.a, bv.a);  ffma2(az1[e], hz1.b, bv.b);
                ffma2(axn0[e], in0.a, av.a); ffma2(axn0[e], in0.b, av.b);
                ffma2(axn1[e], in1.a, av.a); ffma2(axn1[e], in1.b, av.b);
                ffma2(ahn0[e], hn0.a, bv.a); ffma2(ahn0[e], hn0.b, bv.b);
                ffma2(ahn1[e], hn1.a, bv.a); ffma2(ahn1[e], hn1.b, bv.b);
            }
        }

        // gates -> h2_new
#pragma unroll
        for (int e = 0; e < EPW; ++e) {
            float r0 = sigmoid_f(hsum2(ar0[e]) + B1r0);
            float r1 = sigmoid_f(hsum2(ar1[e]) + B1r1);
            float z0 = sigmoid_f(hsum2(az0[e]) + B1z0);
            float z1 = sigmoid_f(hsum2(az1[e]) + B1z1);
            float n0 = tanh_f(fmaf(r0, hsum2(ahn0[e]) + B1hn0, hsum2(axn0[e]) + B1xn0));
            float n1 = tanh_f(fmaf(r1, hsum2(ahn1[e]) + B1hn1, hsum2(axn1[e]) + B1xn1));
            float hp0 = s_h2[e * Hn + lane];
            float hp1 = s_h2[e * Hn + lane + 32];
            hA[e] = fmaf(z0, hp0 - n0, n0);
            hB[e] = fmaf(z1, hp1 - n1, n1);
        }
        __syncwarp();
#pragma unroll
        for (int e = 0; e < EPW; ++e) {
            s_h2[e * Hn + lane]      = hA[e];
            s_h2[e * Hn + lane + 32] = hB[e];
        }
        __syncwarp();
    }

    // ---- FC head ----
    const float fw0 = fc_w[lane];
    const float fw1 = fc_w[lane + 32];
    const float fb  = fc_b[0];
#pragma unroll
    for (int e = 0; e < EPW; ++e) {
        float v = fw0 * s_h2[e * Hn + lane] + fw1 * s_h2[e * Hn + lane + 32];
#pragma unroll
        for (int off = 16; off > 0; off >>= 1)
            v += __shfl_xor_sync(0xffffffffu, v, off);
        if (lane == 0) out[eb + e] = v + fb;
    }
}

extern "C" void kernel_launch(void* const* d_in, const int* in_sizes, int n_in,
                              void* d_out, int out_size)
{
    const float* x     = (const float*)d_in[0];
    const float* W_ih0 = (const float*)d_in[1];
    const float* W_hh0 = (const float*)d_in[2];
    const float* b_ih0 = (const float*)d_in[3];
    const float* b_hh0 = (const float*)d_in[4];
    const float* W_ih1 = (const float*)d_in[5];
    const float* W_hh1 = (const float*)d_in[6];
    const float* b_ih1 = (const float*)d_in[7];
    const float* b_hh1 = (const float*)d_in[8];
    const float* fc_w  = (const float*)d_in[9];
    const float* fc_b  = (const float*)d_in[10];
    float* out = (float*)d_out;

    int batch = in_sizes[0] / (Tn * Dn);   // 4096
    int grid = batch / EPB;                // 128 blocks

    size_t smem = (size_t)SMEM_FLOATS * sizeof(float);  // 192512 B
    cudaFuncSetAttribute(gru_fused_kernel,
                         cudaFuncAttributeMaxDynamicSharedMemorySize, (int)smem);

    gru_fused_kernel<<<grid, TPB, smem>>>(x, W_ih0, W_hh0, b_ih0, b_hh0,
                                          W_ih1, W_hh1, b_ih1, b_hh1,
                                          fc_w, fc_b, out);
}

// round 7
// speedup vs baseline: 2.0347x; 1.1295x over previous
#include <cuda_runtime.h>

typedef unsigned long long u64;

#define Bn 4096
#define Tn 128
#define Dn 32
#define Hn 64
#define Gn 192   // 3*H

#define NWARP 8
#define TPB (NWARP * 32)  // 256 threads
#define NPAIR 4           // warp pairs per block
#define EPW 8             // batch elements per warp PAIR
#define EPB (NPAIR * EPW) // 32 elements per block

// Weight layout: s[(k>>2)*768 + g*4 + (k&3)] = W[g][k]   (quad-of-k packed per row)
#define OFF_W0X 0                        // [8][192][4]  = 6144
#define OFF_W0H (OFF_W0X + 8  * 768)    // 12288
#define OFF_W1I (OFF_W0H + 16 * 768)
#define OFF_W1H (OFF_W1I + 16 * 768)
#define OFF_H1  (OFF_W1H + 16 * 768)    // 43008: [4 pair][2 buf][8 e][64]
#define OFF_H2  (OFF_H1 + NPAIR * 2 * EPW * Hn)   // +4096 = 47104
#define OFF_X   (OFF_H2 + NPAIR * 2 * EPW * Hn)   // +4096 = 51200: [8 warp][8 e][32]
#define SMEM_FLOATS (OFF_X + NWARP * EPW * Dn)    // +2048 = 53248 floats = 212992 B

__device__ __forceinline__ void ffma2(u64& d, u64 a, u64 b) {
    asm("fma.rn.f32x2 %0, %1, %2, %0;" : "+l"(d) : "l"(a), "l"(b));
}
__device__ __forceinline__ float hsum2(u64 v) {
    float lo, hi;
    asm("mov.b64 {%0, %1}, %2;" : "=f"(lo), "=f"(hi) : "l"(v));
    return lo + hi;
}
__device__ __forceinline__ float sigmoid_f(float x) {
    return __fdividef(1.0f, 1.0f + __expf(-x));
}
__device__ __forceinline__ float tanh_f(float x) {
    float e = __expf(-2.0f * x);
    return __fdividef(1.0f - e, 1.0f + e);
}

struct u64x2 { u64 a, b; };
__device__ __forceinline__ u64x2 lds128(const float* p) {
    u64x2 r;
    ulonglong2 v = *(const ulonglong2*)p;
    r.a = v.x; r.b = v.y;
    return r;
}

__global__ void __launch_bounds__(TPB, 1)
gru_fused_kernel(const float* __restrict__ x,
                 const float* __restrict__ W_ih0, const float* __restrict__ W_hh0,
                 const float* __restrict__ b_ih0, const float* __restrict__ b_hh0,
                 const float* __restrict__ W_ih1, const float* __restrict__ W_hh1,
                 const float* __restrict__ b_ih1, const float* __restrict__ b_hh1,
                 const float* __restrict__ fc_w, const float* __restrict__ fc_b,
                 float* __restrict__ out)
{
    extern __shared__ float sm[];
    const int tid = threadIdx.x;

    // ---- stage weights ----
    for (int idx = tid; idx < Gn * Dn; idx += TPB) {
        int g = idx / Dn, k = idx - g * Dn;
        sm[OFF_W0X + (k >> 2) * 768 + g * 4 + (k & 3)] = W_ih0[idx];
    }
    for (int idx = tid; idx < Gn * Hn; idx += TPB) {
        int g = idx / Hn, k = idx - g * Hn;
        int d = (k >> 2) * 768 + g * 4 + (k & 3);
        sm[OFF_W0H + d] = W_hh0[idx];
        sm[OFF_W1I + d] = W_ih1[idx];
        sm[OFF_W1H + d] = W_hh1[idx];
    }
    __syncthreads();

    const int warp = tid >> 5;
    const int lane = tid & 31;
    const int wg = warp & 3;          // pair id (element group)
    const int hw = warp >> 2;         // row half: 0 or 1
    const int barid = 1 + wg;
    const int eb = blockIdx.x * EPB + wg * EPW;

    const int row = lane + 32 * hw;   // this warp's row within each gate

    // h buffers: [pair][buf][e][64]
    float* h1b = sm + OFF_H1 + wg * (2 * EPW * Hn);
    float* h2b = sm + OFF_H2 + wg * (2 * EPW * Hn);
    float* s_x = sm + OFF_X  + warp * (EPW * Dn);   // per-warp private copy

    // zero the read buffer (buf 0) of h1/h2
#pragma unroll
    for (int e = 0; e < EPW; ++e) {
        h1b[e * Hn + row] = 0.0f;
        h2b[e * Hn + row] = 0.0f;
    }
    __syncthreads();   // also covers weight staging ordering for all warps

    // biases for this warp's rows
    const float Br0  = b_ih0[row]       + b_hh0[row];
    const float Bz0  = b_ih0[row + 64]  + b_hh0[row + 64];
    const float Bxn0 = b_ih0[row + 128];
    const float Bhn0 = b_hh0[row + 128];
    const float Br1  = b_ih1[row]       + b_hh1[row];
    const float Bz1  = b_ih1[row + 64]  + b_hh1[row + 64];
    const float Bxn1 = b_ih1[row + 128];
    const float Bhn1 = b_hh1[row + 160 - 32];   // = row+128
    // (identical expression; keep simple)

    // weight float4-base offsets within a quad block (float units)
    const int oR = row * 4;
    const int oZ = (row + 64) * 4;
    const int oN = (row + 128) * 4;

    u64 ar[EPW], az[EPW], axn[EPW], ahn[EPW];

    // prefetch t=0 x
    float xr[EPW];
#pragma unroll
    for (int e = 0; e < EPW; ++e)
        xr[e] = x[(eb + e) * (Tn * Dn) + lane];

    int rd = 0;   // read-buffer parity

    for (int t = 0; t < Tn; ++t) {
        const float* h1r = h1b + rd * (EPW * Hn);
        float*       h1w = h1b + (1 - rd) * (EPW * Hn);
        const float* h2r = h2b + rd * (EPW * Hn);
        float*       h2w = h2b + (1 - rd) * (EPW * Hn);

        // stage x (warp-private), prefetch next t
#pragma unroll
        for (int e = 0; e < EPW; ++e)
            s_x[e * Dn + lane] = xr[e];
        __syncwarp();
        if (t + 1 < Tn) {
#pragma unroll
            for (int e = 0; e < EPW; ++e)
                xr[e] = x[((eb + e) * Tn + t + 1) * Dn + lane];
        }

        // ================= layer 0 =================
#pragma unroll
        for (int e = 0; e < EPW; ++e) { ar[e] = 0; az[e] = 0; axn[e] = 0; ahn[e] = 0; }

#pragma unroll 2
        for (int q = 0; q < Dn / 4; ++q) {
            const float* wq = sm + OFF_W0X + q * 768;
            u64x2 wr = lds128(wq + oR);
            u64x2 wz = lds128(wq + oZ);
            u64x2 wn = lds128(wq + oN);
#pragma unroll
            for (int e = 0; e < EPW; ++e) {
                u64x2 xv = lds128(s_x + e * Dn + q * 4);   // broadcast
                ffma2(ar[e],  wr.a, xv.a); ffma2(ar[e],  wr.b, xv.b);
                ffma2(az[e],  wz.a, xv.a); ffma2(az[e],  wz.b, xv.b);
                ffma2(axn[e], wn.a, xv.a); ffma2(axn[e], wn.b, xv.b);
            }
        }
#pragma unroll 2
        for (int q = 0; q < Hn / 4; ++q) {
            const float* wq = sm + OFF_W0H + q * 768;
            u64x2 wr = lds128(wq + oR);
            u64x2 wz = lds128(wq + oZ);
            u64x2 wn = lds128(wq + oN);
#pragma unroll
            for (int e = 0; e < EPW; ++e) {
                u64x2 hv = lds128(h1r + e * Hn + q * 4);   // broadcast
                ffma2(ar[e],  wr.a, hv.a); ffma2(ar[e],  wr.b, hv.b);
                ffma2(az[e],  wz.a, hv.a); ffma2(az[e],  wz.b, hv.b);
                ffma2(ahn[e], wn.a, hv.a); ffma2(ahn[e], wn.b, hv.b);
            }
        }

        // gate epilogue -> h1_new (own row only), write to alternate buffer
#pragma unroll
        for (int e = 0; e < EPW; ++e) {
            float r = sigmoid_f(hsum2(ar[e]) + Br0);
            float z = sigmoid_f(hsum2(az[e]) + Bz0);
            float n = tanh_f(fmaf(r, hsum2(ahn[e]) + Bhn0, hsum2(axn[e]) + Bxn0));
            float hp = h1r[e * Hn + row];
            h1w[e * Hn + row] = fmaf(z, hp - n, n);
        }

        // the ONE cross-warp barrier per timestep: h1_new visible to pair peer
        asm volatile("bar.sync %0, %1;" :: "r"(barid), "r"(64) : "memory");

        // ================= layer 1 =================
#pragma unroll
        for (int e = 0; e < EPW; ++e) { ar[e] = 0; az[e] = 0; axn[e] = 0; ahn[e] = 0; }

#pragma unroll 1
        for (int q = 0; q < Hn / 4; ++q) {
            const float* wqi = sm + OFF_W1I + q * 768;
            const float* wqh = sm + OFF_W1H + q * 768;
            u64x2 ir = lds128(wqi + oR);
            u64x2 iz = lds128(wqi + oZ);
            u64x2 in = lds128(wqi + oN);
            u64x2 hr = lds128(wqh + oR);
            u64x2 hz = lds128(wqh + oZ);
            u64x2 hn = lds128(wqh + oN);
#pragma unroll
            for (int e = 0; e < EPW; ++e) {
                u64x2 av = lds128(h1w + e * Hn + q * 4);   // new h1 (layer-1 input)
                u64x2 bv = lds128(h2r + e * Hn + q * 4);   // prev h2
                ffma2(ar[e],  ir.a, av.a); ffma2(ar[e],  ir.b, av.b);
                ffma2(ar[e],  hr.a, bv.a); ffma2(ar[e],  hr.b, bv.b);
                ffma2(az[e],  iz.a, av.a); ffma2(az[e],  iz.b, av.b);
                ffma2(az[e],  hz.a, bv.a); ffma2(az[e],  hz.b, bv.b);
                ffma2(axn[e], in.a, av.a); ffma2(axn[e], in.b, av.b);
                ffma2(ahn[e], hn.a, bv.a); ffma2(ahn[e], hn.b, bv.b);
            }
        }

#pragma unroll
        for (int e = 0; e < EPW; ++e) {
            float r = sigmoid_f(hsum2(ar[e]) + Br1);
            float z = sigmoid_f(hsum2(az[e]) + Bz1);
            float n = tanh_f(fmaf(r, hsum2(ahn[e]) + Bhn1, hsum2(axn[e]) + Bxn1));
            float hp = h2r[e * Hn + row];
            h2w[e * Hn + row] = fmaf(z, hp - n, n);
        }

        rd ^= 1;
    }

    // final h2 lives in buffer 'rd' (last write went to 1-rd_old = rd_new)
    asm volatile("bar.sync %0, %1;" :: "r"(barid), "r"(64) : "memory");

    if (hw == 0) {
        const float* h2f = h2b + rd * (EPW * Hn);
        const float fw0 = fc_w[lane];
        const float fw1 = fc_w[lane + 32];
        const float fb  = fc_b[0];
#pragma unroll
        for (int e = 0; e < EPW; ++e) {
            float v = fw0 * h2f[e * Hn + lane] + fw1 * h2f[e * Hn + lane + 32];
#pragma unroll
            for (int off = 16; off > 0; off >>= 1)
                v += __shfl_xor_sync(0xffffffffu, v, off);
            if (lane == 0) out[eb + e] = v + fb;
        }
    }
}

extern "C" void kernel_launch(void* const* d_in, const int* in_sizes, int n_in,
                              void* d_out, int out_size)
{
    const float* x     = (const float*)d_in[0];
    const float* W_ih0 = (const float*)d_in[1];
    const float* W_hh0 = (const float*)d_in[2];
    const float* b_ih0 = (const float*)d_in[3];
    const float* b_hh0 = (const float*)d_in[4];
    const float* W_ih1 = (const float*)d_in[5];
    const float* W_hh1 = (const float*)d_in[6];
    const float* b_ih1 = (const float*)d_in[7];
    const float* b_hh1 = (const float*)d_in[8];
    const float* fc_w  = (const float*)d_in[9];
    const float* fc_b  = (const float*)d_in[10];
    float* out = (float*)d_out;

    int batch = in_sizes[0] / (Tn * Dn);   // 4096
    int grid = batch / EPB;                // 128 blocks

    size_t smem = (size_t)SMEM_FLOATS * sizeof(float);  // 212992 B
    cudaFuncSetAttribute(gru_fused_kernel,
                         cudaFuncAttributeMaxDynamicSharedMemorySize, (int)smem);

    gru_fused_kernel<<<grid, TPB, smem>>>(x, W_ih0, W_hh0, b_ih0, b_hh0,
                                          W_ih1, W_hh1, b_ih1, b_hh1,
                                          fc_w, fc_b, out);
}